// round 12
// baseline (speedup 1.0000x reference)
#include <cuda_runtime.h>
#include <cuda_fp16.h>
#include <mma.h>
#include <cstdint>

using namespace nvcuda;

#define NUSR 100000
#define NBIZ 20000
#define NUSR_PAD 100096
#define NBIZ_PAD 20096
#define EUB  3200000
#define EUU  1600000
#define EBB  320000
#define EALL (EUB + EUU + EBB)
#define INDIM 384
#define D    128
#define DH   64

__device__ float g_uS[(size_t)NUSR_PAD * D];
__device__ float g_bS[(size_t)NBIZ_PAD * D];
__device__ __half2 g_uh0[(size_t)NUSR_PAD * DH];
__device__ __half2 g_uh1[(size_t)NUSR_PAD * DH];
__device__ __half2 g_uh2[(size_t)NUSR_PAD * DH];
__device__ __half2 g_bh0[(size_t)NBIZ_PAD * DH];
__device__ __half2 g_bh1[(size_t)NBIZ_PAD * DH];
__device__ __half2 g_bh2[(size_t)NBIZ_PAD * DH];

__device__ int  g_bu_ptr[NUSR + 1];
__device__ int2 g_bu_cv[EUB];
__device__ int  g_uu_ptr[NUSR + 1];
__device__ int2 g_uu_cv[EUU];
__device__ int  g_ub_ptr[NBIZ + 1];
__device__ int2 g_ub_cv[EUB];
__device__ int  g_bb_ptr[NBIZ + 1];
__device__ int2 g_bb_cv[EBB];

#define OFF_BU 0
#define OFF_UU NUSR
#define OFF_UB (2 * NUSR)
#define OFF_BB (2 * NUSR + NBIZ)
#define CNT4_TOT (2 * NUSR + 2 * NBIZ)
__device__ int g_cnt4[CNT4_TOT];
__device__ int g_part4[4 * 128];

// ================= CSR build (fully batched) ==================================
__global__ void hist_all_kernel(const int* __restrict__ ub_u, const int* __restrict__ ub_b,
                                const int* __restrict__ uu_dst, const int* __restrict__ bb_dst,
                                int* __restrict__ cnt4) {
    int i = blockIdx.x * blockDim.x + threadIdx.x;
    if (i < EUB) {
        atomicAdd(&cnt4[OFF_BU + ub_u[i]], 1);
        atomicAdd(&cnt4[OFF_UB + ub_b[i]], 1);
    } else if (i < EUB + EUU) {
        atomicAdd(&cnt4[OFF_UU + uu_dst[i - EUB]], 1);
    } else if (i < EALL) {
        atomicAdd(&cnt4[OFF_BB + bb_dst[i - EUB - EUU]], 1);
    }
}

#define SCAN_BLK 1024
__global__ void scan1_4_kernel(const int* __restrict__ cnt4,
                               int* __restrict__ bu_ptr, int* __restrict__ uu_ptr,
                               int* __restrict__ ub_ptr, int* __restrict__ bb_ptr,
                               int* __restrict__ part4) {
    __shared__ int sh[SCAN_BLK];
    const int y = blockIdx.y;
    const int off = (y == 0) ? OFF_BU : (y == 1) ? OFF_UU : (y == 2) ? OFF_UB : OFF_BB;
    const int n   = (y < 2) ? NUSR : NBIZ;
    int* out = (y == 0) ? bu_ptr : (y == 1) ? uu_ptr : (y == 2) ? ub_ptr : bb_ptr;
    int i = blockIdx.x * SCAN_BLK + threadIdx.x;
    int v = (i < n) ? cnt4[off + i] : 0;
    sh[threadIdx.x] = v;
    __syncthreads();
#pragma unroll
    for (int o = 1; o < SCAN_BLK; o <<= 1) {
        int t = (threadIdx.x >= o) ? sh[threadIdx.x - o] : 0;
        __syncthreads();
        sh[threadIdx.x] += t;
        __syncthreads();
    }
    if (i < n) out[i] = sh[threadIdx.x] - v;
    if (threadIdx.x == SCAN_BLK - 1) part4[y * 128 + blockIdx.x] = sh[threadIdx.x];
}

__global__ void scan2_4_kernel(int* __restrict__ part4) {
    __shared__ int sh[128];
    const int y = blockIdx.y;
    const int nb = (y < 2) ? ((NUSR + SCAN_BLK - 1) / SCAN_BLK)
                           : ((NBIZ + SCAN_BLK - 1) / SCAN_BLK);
    int v = (threadIdx.x < nb) ? part4[y * 128 + threadIdx.x] : 0;
    sh[threadIdx.x] = v;
    __syncthreads();
#pragma unroll
    for (int o = 1; o < 128; o <<= 1) {
        int t = (threadIdx.x >= o) ? sh[threadIdx.x - o] : 0;
        __syncthreads();
        sh[threadIdx.x] += t;
        __syncthreads();
    }
    if (threadIdx.x < nb) part4[y * 128 + threadIdx.x] = sh[threadIdx.x] - v;
}

__global__ void scan3_4_kernel(int* __restrict__ bu_ptr, int* __restrict__ uu_ptr,
                               int* __restrict__ ub_ptr, int* __restrict__ bb_ptr,
                               const int* __restrict__ part4) {
    const int y = blockIdx.y;
    const int n = (y < 2) ? NUSR : NBIZ;
    const int E = (y == 0) ? EUB : (y == 1) ? EUU : (y == 2) ? EUB : EBB;
    int* out = (y == 0) ? bu_ptr : (y == 1) ? uu_ptr : (y == 2) ? ub_ptr : bb_ptr;
    int i = blockIdx.x * blockDim.x + threadIdx.x;
    if (i < n) out[i] += part4[y * 128 + i / SCAN_BLK];
    if (i == 0) out[n] = E;
}

__global__ void fill_all_kernel(const int* __restrict__ ub_u, const int* __restrict__ ub_b,
                                const float* __restrict__ val_ub, const float* __restrict__ val_bu,
                                const int* __restrict__ uu_src, const int* __restrict__ uu_dst,
                                const float* __restrict__ uu_val,
                                const int* __restrict__ bb_src, const int* __restrict__ bb_dst,
                                const float* __restrict__ bb_val,
                                const int* __restrict__ bu_ptr, const int* __restrict__ uu_ptr,
                                const int* __restrict__ ub_ptr, const int* __restrict__ bb_ptr,
                                int* __restrict__ cnt4,
                                int2* __restrict__ bu_cv, int2* __restrict__ uu_cv,
                                int2* __restrict__ ub_cv, int2* __restrict__ bb_cv) {
    int i = blockIdx.x * blockDim.x + threadIdx.x;
    if (i < EUB) {
        int u = ub_u[i];
        int b = ub_b[i];
        int pu = bu_ptr[u] + atomicSub(&cnt4[OFF_BU + u], 1) - 1;
        bu_cv[pu] = make_int2(b, __float_as_int(val_bu[i]));
        int pb = ub_ptr[b] + atomicSub(&cnt4[OFF_UB + b], 1) - 1;
        ub_cv[pb] = make_int2(u, __float_as_int(val_ub[i]));
    } else if (i < EUB + EUU) {
        int j = i - EUB;
        int d = uu_dst[j];
        int pos = uu_ptr[d] + atomicSub(&cnt4[OFF_UU + d], 1) - 1;
        uu_cv[pos] = make_int2(uu_src[j], __float_as_int(uu_val[j]));
    } else if (i < EALL) {
        int j = i - EUB - EUU;
        int d = bb_dst[j];
        int pos = bb_ptr[d] + atomicSub(&cnt4[OFF_BB + d], 1) - 1;
        bb_cv[pos] = make_int2(bb_src[j], __float_as_int(bb_val[j]));
    }
}

// ================= tensor-core GEMM + fused f2h ==============================
#define GBM 128
#define GBK 16
__global__ void gemm_tc_kernel(const float* __restrict__ A,
                               const float* __restrict__ W,
                               float* __restrict__ S,
                               __half2* __restrict__ H, int M) {
    __shared__ __half Ash[GBM][GBK + 8];
    __shared__ __half Wsh[GBK][D + 8];
    const int tid  = threadIdx.x;
    const int warp = tid >> 5;
    const int wr   = warp >> 1;
    const int wc   = warp & 1;
    const int row0 = blockIdx.x * GBM;

    wmma::fragment<wmma::accumulator, 16, 16, 16, float> acc[2][4];
#pragma unroll
    for (int r = 0; r < 2; r++)
#pragma unroll
        for (int c = 0; c < 4; c++) wmma::fill_fragment(acc[r][c], 0.0f);

    for (int k0 = 0; k0 < INDIM; k0 += GBK) {
#pragma unroll
        for (int i = 0; i < 8; i++) {
            int idx = tid + i * 256;
            int r  = idx >> 4;
            int kk = idx & 15;
            int gr = row0 + r;
            float a = (gr < M) ? __ldg(A + (size_t)gr * INDIM + k0 + kk) : 0.f;
            Ash[r][kk] = __float2half_rn(a);
        }
#pragma unroll
        for (int i = 0; i < 8; i++) {
            int idx = tid + i * 256;
            int kk = idx >> 7;
            int c  = idx & 127;
            Wsh[kk][c] = __float2half_rn(__ldg(W + (size_t)(k0 + kk) * D + c));
        }
        __syncthreads();

        wmma::fragment<wmma::matrix_a, 16, 16, 16, __half, wmma::row_major> fa[2];
        wmma::fragment<wmma::matrix_b, 16, 16, 16, __half, wmma::row_major> fb[4];
#pragma unroll
        for (int r = 0; r < 2; r++)
            wmma::load_matrix_sync(fa[r], &Ash[wr * 32 + r * 16][0], GBK + 8);
#pragma unroll
        for (int c = 0; c < 4; c++)
            wmma::load_matrix_sync(fb[c], &Wsh[0][wc * 64 + c * 16], D + 8);
#pragma unroll
        for (int r = 0; r < 2; r++)
#pragma unroll
            for (int c = 0; c < 4; c++)
                wmma::mma_sync(acc[r][c], fa[r], fb[c], acc[r][c]);
        __syncthreads();
    }
#pragma unroll
    for (int r = 0; r < 2; r++)
#pragma unroll
        for (int c = 0; c < 4; c++)
            wmma::store_matrix_sync(
                S + (size_t)(row0 + wr * 32 + r * 16) * D + wc * 64 + c * 16,
                acc[r][c], D, wmma::mem_row_major);
    __syncthreads();
    const int n4 = GBM * D / 4;
    for (int i = tid; i < n4; i += 256) {
        float4 v = reinterpret_cast<const float4*>(S + (size_t)row0 * D)[i];
        uint2 h;
        __half2 h0 = __float22half2_rn(make_float2(v.x, v.y));
        __half2 h1 = __float22half2_rn(make_float2(v.z, v.w));
        h.x = *reinterpret_cast<uint32_t*>(&h0);
        h.y = *reinterpret_cast<uint32_t*>(&h1);
        reinterpret_cast<uint2*>(H + (size_t)row0 * DH)[i] = h;
    }
}

// ================= fused gather SpMM (paired edges, 128-bit loads) ===========
// Half-warp per edge: lanes 0-15 process even edges, 16-31 odd edges.
// Each lane gathers a 16B fragment (8 halfs, cols [8*hl, 8*hl+8)) via LDG.128.
// Accumulate 8 fp32 per lane; halves merged by shfl_xor(16) at row end.
__device__ __forceinline__ void gather_row_pair(const int* __restrict__ ptr,
                                                const int2* __restrict__ cv,
                                                const __half2* __restrict__ x,
                                                int row, int lane, int half, int hl,
                                                float acc[8]) {
    int s = __ldg(ptr + row);
    int e = __ldg(ptr + row + 1);
    for (int base = s; base < e; base += 32) {
        int rem = e - base;   // > 0, warp-uniform
        int c = 0; float v = 0.f;
        if (lane < rem) {
            int2 p = __ldg(cv + base + lane);
            c = p.x; v = __int_as_float(p.y);
        }
#pragma unroll
        for (int jb = 0; jb < 32; jb += 8) {
            if (jb >= rem) break;   // warp-uniform (8-edge granularity)
#pragma unroll
            for (int jj = 0; jj < 4; jj++) {
                int src = jb + jj * 2 + half;   // edge this half processes
                int   cj = __shfl_sync(0xffffffffu, c, src);
                float vj = __shfl_sync(0xffffffffu, v, src);
                uint4 raw = __ldg(reinterpret_cast<const uint4*>(x + (size_t)cj * DH) + hl);
                __half2 q0 = *reinterpret_cast<__half2*>(&raw.x);
                __half2 q1 = *reinterpret_cast<__half2*>(&raw.y);
                __half2 q2 = *reinterpret_cast<__half2*>(&raw.z);
                __half2 q3 = *reinterpret_cast<__half2*>(&raw.w);
                float2 f0 = __half22float2(q0);
                float2 f1 = __half22float2(q1);
                float2 f2 = __half22float2(q2);
                float2 f3 = __half22float2(q3);
                acc[0] += vj * f0.x; acc[1] += vj * f0.y;
                acc[2] += vj * f1.x; acc[3] += vj * f1.y;
                acc[4] += vj * f2.x; acc[5] += vj * f2.y;
                acc[6] += vj * f3.x; acc[7] += vj * f3.y;
            }
        }
    }
}

__global__ void spmm_layer_kernel(const int* __restrict__ bu_ptr, const int2* __restrict__ bu_cv,
                                  const int* __restrict__ uu_ptr, const int2* __restrict__ uu_cv,
                                  const int* __restrict__ ub_ptr, const int2* __restrict__ ub_cv,
                                  const int* __restrict__ bb_ptr, const int2* __restrict__ bb_cv,
                                  const __half2* __restrict__ u_cur,
                                  const __half2* __restrict__ b_cur,
                                  __half2* __restrict__ u_new,
                                  __half2* __restrict__ b_new,
                                  const __half2* __restrict__ u0, const __half2* __restrict__ u1,
                                  const __half2* __restrict__ b0, const __half2* __restrict__ b1,
                                  float* __restrict__ out, int final_layer) {
    const int lane = threadIdx.x & 31;
    const int half = lane >> 4;
    const int hl   = lane & 15;
    const int w = (blockIdx.x * blockDim.x + threadIdx.x) >> 5;
    if (w >= NUSR + NBIZ) return;
    float acc[8];
#pragma unroll
    for (int i = 0; i < 8; i++) acc[i] = 0.f;
    const bool is_user = (w < NUSR);
    const int row = is_user ? w : (w - NUSR);
    if (is_user) {
        gather_row_pair(bu_ptr, bu_cv, b_cur, row, lane, half, hl, acc);
        gather_row_pair(uu_ptr, uu_cv, u_cur, row, lane, half, hl, acc);
    } else {
        gather_row_pair(ub_ptr, ub_cv, u_cur, row, lane, half, hl, acc);
        gather_row_pair(bb_ptr, bb_cv, b_cur, row, lane, half, hl, acc);
    }
    // merge even/odd edge partials (lanes k and k+16 cover same columns)
#pragma unroll
    for (int i = 0; i < 8; i++)
        acc[i] += __shfl_xor_sync(0xffffffffu, acc[i], 16);

    if (!final_layer) {
        if (half == 0) {
            uint4 h;
            __half2 h0 = __float22half2_rn(make_float2(acc[0], acc[1]));
            __half2 h1 = __float22half2_rn(make_float2(acc[2], acc[3]));
            __half2 h2 = __float22half2_rn(make_float2(acc[4], acc[5]));
            __half2 h3 = __float22half2_rn(make_float2(acc[6], acc[7]));
            h.x = *reinterpret_cast<uint32_t*>(&h0);
            h.y = *reinterpret_cast<uint32_t*>(&h1);
            h.z = *reinterpret_cast<uint32_t*>(&h2);
            h.w = *reinterpret_cast<uint32_t*>(&h3);
            __half2* dst = is_user ? u_new : b_new;
            *(reinterpret_cast<uint4*>(dst + (size_t)row * DH) + hl) = h;
        }
    } else {
        // sum = x0 + x1 + x2 + acc ; out = l2norm(sum * 0.25)
        const __half2* p0 = is_user ? u0 : b0;
        const __half2* p1 = is_user ? u1 : b1;
        const __half2* p2 = is_user ? u_cur : b_cur;
        float s[8];
        if (half == 0) {
            uint4 r0 = __ldg(reinterpret_cast<const uint4*>(p0 + (size_t)row * DH) + hl);
            uint4 r1 = __ldg(reinterpret_cast<const uint4*>(p1 + (size_t)row * DH) + hl);
            uint4 r2 = __ldg(reinterpret_cast<const uint4*>(p2 + (size_t)row * DH) + hl);
            const uint32_t* a0 = &r0.x;
            const uint32_t* a1 = &r1.x;
            const uint32_t* a2 = &r2.x;
#pragma unroll
            for (int q = 0; q < 4; q++) {
                float2 f0 = __half22float2(*reinterpret_cast<const __half2*>(a0 + q));
                float2 f1 = __half22float2(*reinterpret_cast<const __half2*>(a1 + q));
                float2 f2 = __half22float2(*reinterpret_cast<const __half2*>(a2 + q));
                s[2 * q + 0] = (f0.x + f1.x + f2.x + acc[2 * q + 0]) * 0.25f;
                s[2 * q + 1] = (f0.y + f1.y + f2.y + acc[2 * q + 1]) * 0.25f;
            }
            float ss = 0.f;
#pragma unroll
            for (int i = 0; i < 8; i++) ss += s[i] * s[i];
#pragma unroll
            for (int o = 1; o < 16; o <<= 1) ss += __shfl_xor_sync(0xffffffffu, ss, o);
            float sc = 1.0f / fmaxf(sqrtf(ss), 1e-12f);
            float* outrow = is_user ? (out + (size_t)row * D)
                                    : (out + (size_t)(NUSR + row) * D);
            float4 v0 = make_float4(s[0] * sc, s[1] * sc, s[2] * sc, s[3] * sc);
            float4 v1 = make_float4(s[4] * sc, s[5] * sc, s[6] * sc, s[7] * sc);
            reinterpret_cast<float4*>(outrow)[2 * hl + 0] = v0;
            reinterpret_cast<float4*>(outrow)[2 * hl + 1] = v1;
        }
    }
}

// ================= launcher ====================================================
extern "C" void kernel_launch(void* const* d_in, const int* in_sizes, int n_in,
                              void* d_out, int out_size) {
    const float* user_feat = (const float*)d_in[0];
    const float* biz_feat  = (const float*)d_in[1];
    const float* W_user    = (const float*)d_in[2];
    const float* W_biz     = (const float*)d_in[3];
    const int*   ub_u      = (const int*)  d_in[4];
    const int*   ub_b      = (const int*)  d_in[5];
    const float* val_ub    = (const float*)d_in[6];
    const float* val_bu    = (const float*)d_in[7];
    const int*   uu_src    = (const int*)  d_in[8];
    const int*   uu_dst    = (const int*)  d_in[9];
    const float* uu_val    = (const float*)d_in[10];
    const int*   bb_src    = (const int*)  d_in[11];
    const int*   bb_dst    = (const int*)  d_in[12];
    const float* bb_val    = (const float*)d_in[13];
    float* out = (float*)d_out;

    float *uS, *bS;
    __half2 *uh0, *uh1, *uh2, *bh0, *bh1, *bh2;
    cudaGetSymbolAddress((void**)&uS, g_uS);
    cudaGetSymbolAddress((void**)&bS, g_bS);
    cudaGetSymbolAddress((void**)&uh0, g_uh0);
    cudaGetSymbolAddress((void**)&uh1, g_uh1);
    cudaGetSymbolAddress((void**)&uh2, g_uh2);
    cudaGetSymbolAddress((void**)&bh0, g_bh0);
    cudaGetSymbolAddress((void**)&bh1, g_bh1);
    cudaGetSymbolAddress((void**)&bh2, g_bh2);

    int *bu_ptr, *uu_ptr, *ub_ptr, *bb_ptr, *cnt4, *part4;
    int2 *bu_cv, *uu_cv, *ub_cv, *bb_cv;
    cudaGetSymbolAddress((void**)&bu_ptr, g_bu_ptr);
    cudaGetSymbolAddress((void**)&bu_cv,  g_bu_cv);
    cudaGetSymbolAddress((void**)&uu_ptr, g_uu_ptr);
    cudaGetSymbolAddress((void**)&uu_cv,  g_uu_cv);
    cudaGetSymbolAddress((void**)&ub_ptr, g_ub_ptr);
    cudaGetSymbolAddress((void**)&ub_cv,  g_ub_cv);
    cudaGetSymbolAddress((void**)&bb_ptr, g_bb_ptr);
    cudaGetSymbolAddress((void**)&bb_cv,  g_bb_cv);
    cudaGetSymbolAddress((void**)&cnt4, g_cnt4);
    cudaGetSymbolAddress((void**)&part4, g_part4);

    static cudaStream_t s2 = nullptr;
    static cudaEvent_t evFork = nullptr, evJoin = nullptr;
    if (s2 == nullptr) {
        cudaStreamCreateWithFlags(&s2, cudaStreamNonBlocking);
        cudaEventCreateWithFlags(&evFork, cudaEventDisableTiming);
        cudaEventCreateWithFlags(&evJoin, cudaEventDisableTiming);
    }

    // ---- fork: CSR build chain on s2, GEMM chain on stream 0 ----
    cudaEventRecord(evFork, 0);
    cudaStreamWaitEvent(s2, evFork, 0);

    cudaMemsetAsync(cnt4, 0, CNT4_TOT * sizeof(int), s2);
    hist_all_kernel<<<(EALL + 255) / 256, 256, 0, s2>>>(ub_u, ub_b, uu_dst, bb_dst, cnt4);
    {
        dim3 g1((NUSR + SCAN_BLK - 1) / SCAN_BLK, 4);
        scan1_4_kernel<<<g1, SCAN_BLK, 0, s2>>>(cnt4, bu_ptr, uu_ptr, ub_ptr, bb_ptr, part4);
        dim3 g2(1, 4);
        scan2_4_kernel<<<g2, 128, 0, s2>>>(part4);
        dim3 g3((NUSR + 255) / 256, 4);
        scan3_4_kernel<<<g3, 256, 0, s2>>>(bu_ptr, uu_ptr, ub_ptr, bb_ptr, part4);
    }
    fill_all_kernel<<<(EALL + 255) / 256, 256, 0, s2>>>(
        ub_u, ub_b, val_ub, val_bu, uu_src, uu_dst, uu_val,
        bb_src, bb_dst, bb_val,
        bu_ptr, uu_ptr, ub_ptr, bb_ptr, cnt4,
        bu_cv, uu_cv, ub_cv, bb_cv);
    cudaEventRecord(evJoin, s2);

    // GEMM (+fused f2h) on stream 0, concurrent with CSR build
    gemm_tc_kernel<<<NUSR_PAD / GBM, 256>>>(user_feat, W_user, uS, uh0, NUSR);
    gemm_tc_kernel<<<NBIZ_PAD / GBM, 256>>>(biz_feat,  W_biz,  bS, bh0, NBIZ);

    // ---- join ----
    cudaStreamWaitEvent(0, evJoin, 0);

    const int totWarps = NUSR + NBIZ;
    const int spmmBlocks = (totWarps * 32 + 255) / 256;

    // layer 1: cur = h0, new = h1
    spmm_layer_kernel<<<spmmBlocks, 256>>>(
        bu_ptr, bu_cv, uu_ptr, uu_cv, ub_ptr, ub_cv, bb_ptr, bb_cv,
        uh0, bh0, uh1, bh1, nullptr, nullptr, nullptr, nullptr, out, 0);
    // layer 2: cur = h1, new = h2
    spmm_layer_kernel<<<spmmBlocks, 256>>>(
        bu_ptr, bu_cv, uu_ptr, uu_cv, ub_ptr, ub_cv, bb_ptr, bb_cv,
        uh1, bh1, uh2, bh2, nullptr, nullptr, nullptr, nullptr, out, 0);
    // layer 3 (final): cur = h2; sum h0+h1+h2+acc, l2norm -> out
    spmm_layer_kernel<<<spmmBlocks, 256>>>(
        bu_ptr, bu_cv, uu_ptr, uu_cv, ub_ptr, ub_cv, bb_ptr, bb_cv,
        uh2, bh2, nullptr, nullptr, uh0, uh1, bh0, bh1, out, 1);

    (void)n_in; (void)in_sizes; (void)out_size;
}

// round 13
// speedup vs baseline: 1.1673x; 1.1673x over previous
#include <cuda_runtime.h>
#include <cuda_fp16.h>
#include <mma.h>
#include <cstdint>

using namespace nvcuda;

#define NUSR 100000
#define NBIZ 20000
#define NUSR_PAD 100096
#define NBIZ_PAD 20096
#define EUB  3200000
#define EUU  1600000
#define EBB  320000
#define EALL (EUB + EUU + EBB)
#define INDIM 384
#define D    128
#define DH   64

// per-layer fp16 features: 0 = GEMM output, 1 = layer1, 2 = layer2
__device__ __half2 g_uh0[(size_t)NUSR_PAD * DH];
__device__ __half2 g_uh1[(size_t)NUSR_PAD * DH];
__device__ __half2 g_uh2[(size_t)NUSR_PAD * DH];
__device__ __half2 g_bh0[(size_t)NBIZ_PAD * DH];
__device__ __half2 g_bh1[(size_t)NBIZ_PAD * DH];
__device__ __half2 g_bh2[(size_t)NBIZ_PAD * DH];

__device__ int  g_bu_ptr[NUSR + 1];
__device__ int2 g_bu_cv[EUB];
__device__ int  g_uu_ptr[NUSR + 1];
__device__ int2 g_uu_cv[EUU];
__device__ int  g_ub_ptr[NBIZ + 1];
__device__ int2 g_ub_cv[EUB];
__device__ int  g_bb_ptr[NBIZ + 1];
__device__ int2 g_bb_cv[EBB];

#define OFF_BU 0
#define OFF_UU NUSR
#define OFF_UB (2 * NUSR)
#define OFF_BB (2 * NUSR + NBIZ)
#define CNT4_TOT (2 * NUSR + 2 * NBIZ)
__device__ int g_cnt4[CNT4_TOT];
__device__ int g_part4[4 * 128];

// ================= CSR build (fully batched) ==================================
__global__ void hist_all_kernel(const int* __restrict__ ub_u, const int* __restrict__ ub_b,
                                const int* __restrict__ uu_dst, const int* __restrict__ bb_dst,
                                int* __restrict__ cnt4) {
    int i = blockIdx.x * blockDim.x + threadIdx.x;
    if (i < EUB) {
        atomicAdd(&cnt4[OFF_BU + ub_u[i]], 1);
        atomicAdd(&cnt4[OFF_UB + ub_b[i]], 1);
    } else if (i < EUB + EUU) {
        atomicAdd(&cnt4[OFF_UU + uu_dst[i - EUB]], 1);
    } else if (i < EALL) {
        atomicAdd(&cnt4[OFF_BB + bb_dst[i - EUB - EUU]], 1);
    }
}

#define SCAN_BLK 1024
__global__ void scan1_4_kernel(const int* __restrict__ cnt4,
                               int* __restrict__ bu_ptr, int* __restrict__ uu_ptr,
                               int* __restrict__ ub_ptr, int* __restrict__ bb_ptr,
                               int* __restrict__ part4) {
    __shared__ int sh[SCAN_BLK];
    const int y = blockIdx.y;
    const int off = (y == 0) ? OFF_BU : (y == 1) ? OFF_UU : (y == 2) ? OFF_UB : OFF_BB;
    const int n   = (y < 2) ? NUSR : NBIZ;
    int* out = (y == 0) ? bu_ptr : (y == 1) ? uu_ptr : (y == 2) ? ub_ptr : bb_ptr;
    int i = blockIdx.x * SCAN_BLK + threadIdx.x;
    int v = (i < n) ? cnt4[off + i] : 0;
    sh[threadIdx.x] = v;
    __syncthreads();
#pragma unroll
    for (int o = 1; o < SCAN_BLK; o <<= 1) {
        int t = (threadIdx.x >= o) ? sh[threadIdx.x - o] : 0;
        __syncthreads();
        sh[threadIdx.x] += t;
        __syncthreads();
    }
    if (i < n) out[i] = sh[threadIdx.x] - v;
    if (threadIdx.x == SCAN_BLK - 1) part4[y * 128 + blockIdx.x] = sh[threadIdx.x];
}

__global__ void scan2_4_kernel(int* __restrict__ part4) {
    __shared__ int sh[128];
    const int y = blockIdx.y;
    const int nb = (y < 2) ? ((NUSR + SCAN_BLK - 1) / SCAN_BLK)
                           : ((NBIZ + SCAN_BLK - 1) / SCAN_BLK);
    int v = (threadIdx.x < nb) ? part4[y * 128 + threadIdx.x] : 0;
    sh[threadIdx.x] = v;
    __syncthreads();
#pragma unroll
    for (int o = 1; o < 128; o <<= 1) {
        int t = (threadIdx.x >= o) ? sh[threadIdx.x - o] : 0;
        __syncthreads();
        sh[threadIdx.x] += t;
        __syncthreads();
    }
    if (threadIdx.x < nb) part4[y * 128 + threadIdx.x] = sh[threadIdx.x] - v;
}

__global__ void scan3_4_kernel(int* __restrict__ bu_ptr, int* __restrict__ uu_ptr,
                               int* __restrict__ ub_ptr, int* __restrict__ bb_ptr,
                               const int* __restrict__ part4) {
    const int y = blockIdx.y;
    const int n = (y < 2) ? NUSR : NBIZ;
    const int E = (y == 0) ? EUB : (y == 1) ? EUU : (y == 2) ? EUB : EBB;
    int* out = (y == 0) ? bu_ptr : (y == 1) ? uu_ptr : (y == 2) ? ub_ptr : bb_ptr;
    int i = blockIdx.x * blockDim.x + threadIdx.x;
    if (i < n) out[i] += part4[y * 128 + i / SCAN_BLK];
    if (i == 0) out[n] = E;
}

__global__ void fill_all_kernel(const int* __restrict__ ub_u, const int* __restrict__ ub_b,
                                const float* __restrict__ val_ub, const float* __restrict__ val_bu,
                                const int* __restrict__ uu_src, const int* __restrict__ uu_dst,
                                const float* __restrict__ uu_val,
                                const int* __restrict__ bb_src, const int* __restrict__ bb_dst,
                                const float* __restrict__ bb_val,
                                const int* __restrict__ bu_ptr, const int* __restrict__ uu_ptr,
                                const int* __restrict__ ub_ptr, const int* __restrict__ bb_ptr,
                                int* __restrict__ cnt4,
                                int2* __restrict__ bu_cv, int2* __restrict__ uu_cv,
                                int2* __restrict__ ub_cv, int2* __restrict__ bb_cv) {
    int i = blockIdx.x * blockDim.x + threadIdx.x;
    if (i < EUB) {
        int u = ub_u[i];
        int b = ub_b[i];
        int pu = bu_ptr[u] + atomicSub(&cnt4[OFF_BU + u], 1) - 1;
        bu_cv[pu] = make_int2(b, __float_as_int(val_bu[i]));
        int pb = ub_ptr[b] + atomicSub(&cnt4[OFF_UB + b], 1) - 1;
        ub_cv[pb] = make_int2(u, __float_as_int(val_ub[i]));
    } else if (i < EUB + EUU) {
        int j = i - EUB;
        int d = uu_dst[j];
        int pos = uu_ptr[d] + atomicSub(&cnt4[OFF_UU + d], 1) - 1;
        uu_cv[pos] = make_int2(uu_src[j], __float_as_int(uu_val[j]));
    } else if (i < EALL) {
        int j = i - EUB - EUU;
        int d = bb_dst[j];
        int pos = bb_ptr[d] + atomicSub(&cnt4[OFF_BB + d], 1) - 1;
        bb_cv[pos] = make_int2(bb_src[j], __float_as_int(bb_val[j]));
    }
}

// ================= tensor-core GEMM, direct fp16 output ======================
// fp32 accumulate in tensor cores; convert fragment elementwise to a half
// accumulator fragment (same-shape accumulators share element mapping) and
// store fp16 directly — no fp32 staging buffer, no f2h pass.
#define GBM 128
#define GBK 16
__global__ void gemm_tc_kernel(const float* __restrict__ A,
                               const float* __restrict__ W,
                               __half* __restrict__ H, int M) {
    __shared__ __half Ash[GBM][GBK + 8];
    __shared__ __half Wsh[GBK][D + 8];
    const int tid  = threadIdx.x;
    const int warp = tid >> 5;
    const int wr   = warp >> 1;
    const int wc   = warp & 1;
    const int row0 = blockIdx.x * GBM;

    wmma::fragment<wmma::accumulator, 16, 16, 16, float> acc[2][4];
#pragma unroll
    for (int r = 0; r < 2; r++)
#pragma unroll
        for (int c = 0; c < 4; c++) wmma::fill_fragment(acc[r][c], 0.0f);

    for (int k0 = 0; k0 < INDIM; k0 += GBK) {
#pragma unroll
        for (int i = 0; i < 8; i++) {
            int idx = tid + i * 256;
            int r  = idx >> 4;
            int kk = idx & 15;
            int gr = row0 + r;
            float a = (gr < M) ? __ldg(A + (size_t)gr * INDIM + k0 + kk) : 0.f;
            Ash[r][kk] = __float2half_rn(a);
        }
#pragma unroll
        for (int i = 0; i < 8; i++) {
            int idx = tid + i * 256;
            int kk = idx >> 7;
            int c  = idx & 127;
            Wsh[kk][c] = __float2half_rn(__ldg(W + (size_t)(k0 + kk) * D + c));
        }
        __syncthreads();

        wmma::fragment<wmma::matrix_a, 16, 16, 16, __half, wmma::row_major> fa[2];
        wmma::fragment<wmma::matrix_b, 16, 16, 16, __half, wmma::row_major> fb[4];
#pragma unroll
        for (int r = 0; r < 2; r++)
            wmma::load_matrix_sync(fa[r], &Ash[wr * 32 + r * 16][0], GBK + 8);
#pragma unroll
        for (int c = 0; c < 4; c++)
            wmma::load_matrix_sync(fb[c], &Wsh[0][wc * 64 + c * 16], D + 8);
#pragma unroll
        for (int r = 0; r < 2; r++)
#pragma unroll
            for (int c = 0; c < 4; c++)
                wmma::mma_sync(acc[r][c], fa[r], fb[c], acc[r][c]);
        __syncthreads();
    }
#pragma unroll
    for (int r = 0; r < 2; r++)
#pragma unroll
        for (int c = 0; c < 4; c++) {
            wmma::fragment<wmma::accumulator, 16, 16, 16, __half> hacc;
#pragma unroll
            for (int e = 0; e < hacc.num_elements; e++)
                hacc.x[e] = __float2half_rn(acc[r][c].x[e]);
            wmma::store_matrix_sync(
                H + (size_t)(row0 + wr * 32 + r * 16) * D + wc * 64 + c * 16,
                hacc, D, wmma::mem_row_major);
        }
}

// ================= fused gather SpMM layer (fp16 source rows) ================
__device__ __forceinline__ float4 h2f4(uint2 raw) {
    __half2 p0 = *reinterpret_cast<__half2*>(&raw.x);
    __half2 p1 = *reinterpret_cast<__half2*>(&raw.y);
    float2 f0 = __half22float2(p0);
    float2 f1 = __half22float2(p1);
    return make_float4(f0.x, f0.y, f1.x, f1.y);
}

__device__ __forceinline__ void gather_row_h(const int* __restrict__ ptr,
                                             const int2* __restrict__ cv,
                                             const __half2* __restrict__ x,
                                             int row, int lane, float4& acc) {
    int s = __ldg(ptr + row);
    int e = __ldg(ptr + row + 1);
    for (int base = s; base < e; base += 32) {
        int rem = e - base;   // > 0, warp-uniform
        int c = 0; float v = 0.f;
        if (lane < rem) {
            int2 p = __ldg(cv + base + lane);
            c = p.x; v = __int_as_float(p.y);
        }
#pragma unroll
        for (int jb = 0; jb < 32; jb += 8) {
            if (jb >= rem) break;   // warp-uniform
#pragma unroll
            for (int jj = 0; jj < 8; jj++) {
                int   cj = __shfl_sync(0xffffffffu, c, jb + jj);
                float vj = __shfl_sync(0xffffffffu, v, jb + jj);
                uint2 raw = __ldg(reinterpret_cast<const uint2*>(x + (size_t)cj * DH) + lane);
                float4 f = h2f4(raw);
                acc.x += vj * f.x; acc.y += vj * f.y;
                acc.z += vj * f.z; acc.w += vj * f.w;
            }
        }
    }
}

// blocked warp->row mapping (homogeneous blocks retire cleanly).
// final==0: write fp16 acc to *_new only.
// final==1: out = l2norm((x0+x1+x2+acc) * 0.25) written directly.
__global__ void spmm_layer_kernel(const int* __restrict__ bu_ptr, const int2* __restrict__ bu_cv,
                                  const int* __restrict__ uu_ptr, const int2* __restrict__ uu_cv,
                                  const int* __restrict__ ub_ptr, const int2* __restrict__ ub_cv,
                                  const int* __restrict__ bb_ptr, const int2* __restrict__ bb_cv,
                                  const __half2* __restrict__ u_cur,
                                  const __half2* __restrict__ b_cur,
                                  __half2* __restrict__ u_new,
                                  __half2* __restrict__ b_new,
                                  const __half2* __restrict__ u0, const __half2* __restrict__ u1,
                                  const __half2* __restrict__ b0, const __half2* __restrict__ b1,
                                  float* __restrict__ out, int final_layer) {
    const int lane = threadIdx.x & 31;
    const int w = (blockIdx.x * blockDim.x + threadIdx.x) >> 5;
    if (w >= NUSR + NBIZ) return;
    float4 acc = make_float4(0.f, 0.f, 0.f, 0.f);
    const bool is_user = (w < NUSR);
    const int row = is_user ? w : (w - NUSR);
    if (is_user) {
        gather_row_h(bu_ptr, bu_cv, b_cur, row, lane, acc);
        gather_row_h(uu_ptr, uu_cv, u_cur, row, lane, acc);
    } else {
        gather_row_h(ub_ptr, ub_cv, u_cur, row, lane, acc);
        gather_row_h(bb_ptr, bb_cv, b_cur, row, lane, acc);
    }

    if (!final_layer) {
        uint2 h;
        __half2 h0 = __float22half2_rn(make_float2(acc.x, acc.y));
        __half2 h1 = __float22half2_rn(make_float2(acc.z, acc.w));
        h.x = *reinterpret_cast<uint32_t*>(&h0);
        h.y = *reinterpret_cast<uint32_t*>(&h1);
        __half2* dst = is_user ? u_new : b_new;
        *reinterpret_cast<uint2*>(dst + (size_t)row * DH + lane * 2) = h;
    } else {
        const __half2* p0 = is_user ? u0 : b0;
        const __half2* p1 = is_user ? u1 : b1;
        const __half2* p2 = is_user ? u_cur : b_cur;
        float4 f0 = h2f4(__ldg(reinterpret_cast<const uint2*>(p0 + (size_t)row * DH) + lane));
        float4 f1 = h2f4(__ldg(reinterpret_cast<const uint2*>(p1 + (size_t)row * DH) + lane));
        float4 f2 = h2f4(__ldg(reinterpret_cast<const uint2*>(p2 + (size_t)row * DH) + lane));
        float4 s;
        s.x = (f0.x + f1.x + f2.x + acc.x) * 0.25f;
        s.y = (f0.y + f1.y + f2.y + acc.y) * 0.25f;
        s.z = (f0.z + f1.z + f2.z + acc.z) * 0.25f;
        s.w = (f0.w + f1.w + f2.w + acc.w) * 0.25f;
        float ss = s.x * s.x + s.y * s.y + s.z * s.z + s.w * s.w;
#pragma unroll
        for (int o = 16; o; o >>= 1) ss += __shfl_xor_sync(0xffffffffu, ss, o);
        float sc = 1.0f / fmaxf(sqrtf(ss), 1e-12f);
        s.x *= sc; s.y *= sc; s.z *= sc; s.w *= sc;
        float* outrow = is_user ? (out + (size_t)row * D)
                                : (out + (size_t)(NUSR + row) * D);
        reinterpret_cast<float4*>(outrow)[lane] = s;
    }
}

// ================= launcher ====================================================
extern "C" void kernel_launch(void* const* d_in, const int* in_sizes, int n_in,
                              void* d_out, int out_size) {
    const float* user_feat = (const float*)d_in[0];
    const float* biz_feat  = (const float*)d_in[1];
    const float* W_user    = (const float*)d_in[2];
    const float* W_biz     = (const float*)d_in[3];
    const int*   ub_u      = (const int*)  d_in[4];
    const int*   ub_b      = (const int*)  d_in[5];
    const float* val_ub    = (const float*)d_in[6];
    const float* val_bu    = (const float*)d_in[7];
    const int*   uu_src    = (const int*)  d_in[8];
    const int*   uu_dst    = (const int*)  d_in[9];
    const float* uu_val    = (const float*)d_in[10];
    const int*   bb_src    = (const int*)  d_in[11];
    const int*   bb_dst    = (const int*)  d_in[12];
    const float* bb_val    = (const float*)d_in[13];
    float* out = (float*)d_out;

    __half2 *uh0, *uh1, *uh2, *bh0, *bh1, *bh2;
    cudaGetSymbolAddress((void**)&uh0, g_uh0);
    cudaGetSymbolAddress((void**)&uh1, g_uh1);
    cudaGetSymbolAddress((void**)&uh2, g_uh2);
    cudaGetSymbolAddress((void**)&bh0, g_bh0);
    cudaGetSymbolAddress((void**)&bh1, g_bh1);
    cudaGetSymbolAddress((void**)&bh2, g_bh2);

    int *bu_ptr, *uu_ptr, *ub_ptr, *bb_ptr, *cnt4, *part4;
    int2 *bu_cv, *uu_cv, *ub_cv, *bb_cv;
    cudaGetSymbolAddress((void**)&bu_ptr, g_bu_ptr);
    cudaGetSymbolAddress((void**)&bu_cv,  g_bu_cv);
    cudaGetSymbolAddress((void**)&uu_ptr, g_uu_ptr);
    cudaGetSymbolAddress((void**)&uu_cv,  g_uu_cv);
    cudaGetSymbolAddress((void**)&ub_ptr, g_ub_ptr);
    cudaGetSymbolAddress((void**)&ub_cv,  g_ub_cv);
    cudaGetSymbolAddress((void**)&bb_ptr, g_bb_ptr);
    cudaGetSymbolAddress((void**)&bb_cv,  g_bb_cv);
    cudaGetSymbolAddress((void**)&cnt4, g_cnt4);
    cudaGetSymbolAddress((void**)&part4, g_part4);

    static cudaStream_t s2 = nullptr;
    static cudaEvent_t evFork = nullptr, evJoin = nullptr;
    if (s2 == nullptr) {
        cudaStreamCreateWithFlags(&s2, cudaStreamNonBlocking);
        cudaEventCreateWithFlags(&evFork, cudaEventDisableTiming);
        cudaEventCreateWithFlags(&evJoin, cudaEventDisableTiming);
    }

    // ---- fork: CSR build chain on s2, GEMM chain on stream 0 ----
    cudaEventRecord(evFork, 0);
    cudaStreamWaitEvent(s2, evFork, 0);

    cudaMemsetAsync(cnt4, 0, CNT4_TOT * sizeof(int), s2);
    hist_all_kernel<<<(EALL + 255) / 256, 256, 0, s2>>>(ub_u, ub_b, uu_dst, bb_dst, cnt4);
    {
        dim3 g1((NUSR + SCAN_BLK - 1) / SCAN_BLK, 4);
        scan1_4_kernel<<<g1, SCAN_BLK, 0, s2>>>(cnt4, bu_ptr, uu_ptr, ub_ptr, bb_ptr, part4);
        dim3 g2(1, 4);
        scan2_4_kernel<<<g2, 128, 0, s2>>>(part4);
        dim3 g3((NUSR + 255) / 256, 4);
        scan3_4_kernel<<<g3, 256, 0, s2>>>(bu_ptr, uu_ptr, ub_ptr, bb_ptr, part4);
    }
    fill_all_kernel<<<(EALL + 255) / 256, 256, 0, s2>>>(
        ub_u, ub_b, val_ub, val_bu, uu_src, uu_dst, uu_val,
        bb_src, bb_dst, bb_val,
        bu_ptr, uu_ptr, ub_ptr, bb_ptr, cnt4,
        bu_cv, uu_cv, ub_cv, bb_cv);
    cudaEventRecord(evJoin, s2);

    // GEMM (direct fp16 out) on stream 0, concurrent with CSR build
    gemm_tc_kernel<<<NUSR_PAD / GBM, 256>>>(user_feat, W_user,
                                            reinterpret_cast<__half*>(uh0), NUSR);
    gemm_tc_kernel<<<NBIZ_PAD / GBM, 256>>>(biz_feat,  W_biz,
                                            reinterpret_cast<__half*>(bh0), NBIZ);

    // ---- join ----
    cudaStreamWaitEvent(0, evJoin, 0);

    const int totWarps = NUSR + NBIZ;
    const int spmmBlocks = (totWarps * 32 + 255) / 256;

    // layer 1: cur = h0, new = h1
    spmm_layer_kernel<<<spmmBlocks, 256>>>(
        bu_ptr, bu_cv, uu_ptr, uu_cv, ub_ptr, ub_cv, bb_ptr, bb_cv,
        uh0, bh0, uh1, bh1, nullptr, nullptr, nullptr, nullptr, out, 0);
    // layer 2: cur = h1, new = h2
    spmm_layer_kernel<<<spmmBlocks, 256>>>(
        bu_ptr, bu_cv, uu_ptr, uu_cv, ub_ptr, ub_cv, bb_ptr, bb_cv,
        uh1, bh1, uh2, bh2, nullptr, nullptr, nullptr, nullptr, out, 0);
    // layer 3 (final): cur = h2; sum h0+h1+h2+acc, l2norm -> out
    spmm_layer_kernel<<<spmmBlocks, 256>>>(
        bu_ptr, bu_cv, uu_ptr, uu_cv, ub_ptr, ub_cv, bb_ptr, bb_cv,
        uh2, bh2, nullptr, nullptr, uh0, uh1, bh0, bh1, out, 1);

    (void)n_in; (void)in_sizes; (void)out_size;
}